// round 6
// baseline (speedup 1.0000x reference)
#include <cuda_runtime.h>

#define S_TILE   16
#define KF       32
#define ROWS     48            // S_TILE + KF
#define DCONST   1024
#define D4       256           // full D in float4
#define C4       128           // chunk width in float4 (512 floats)
#define PITCH4   129           // chunk row pitch in float4 (odd -> conflict-free)
#define COLS     48
#define NEG_BIG  -1.0e9f

#define TILE_F4      (ROWS * PITCH4)          // 6192 float4
#define RED_OFF      (TILE_F4 * 4)            // 24768 floats
#define RED_SIZE     (2 * S_TILE * COLS)      // 1536 floats (2 d-groups)
#define W_OFF        (RED_OFF + RED_SIZE)     // 26304 (byte 105216, 16B aligned)
#define SMEM_FLOATS  (W_OFF + S_TILE * COLS * 2)
#define SMEM_BYTES   (SMEM_FLOATS * 4)        // 111360 B -> 2 CTAs/SM

typedef unsigned long long u64;

__device__ __forceinline__ void fma2(u64& d, u64 a, u64 b) {
    asm("fma.rn.f32x2 %0, %1, %2, %0;" : "+l"(d) : "l"(a), "l"(b));
}
__device__ __forceinline__ float sum2(u64 a) {
    float2 v = *reinterpret_cast<float2*>(&a);
    return v.x + v.y;
}

// load one 512-float chunk of 48 rows into smem (coalesced, 6 rows/warp)
__device__ __forceinline__ void load_chunk(float4* __restrict__ tile4,
                                           const float4* __restrict__ in4,
                                           int s0, int cOff, int tid, int S)
{
    const int w    = tid >> 5;
    const int lane = tid & 31;
    #pragma unroll
    for (int rr = 0; rr < 6; ++rr) {
        const int r = w * 6 + rr;
        int gr = s0 + r;
        if (gr > S - 1) gr = S - 1;
        const float4* src = in4 + (size_t)gr * D4 + cOff + lane;
        float4*       dst = tile4 + r * PITCH4 + lane;
        #pragma unroll
        for (int c = 0; c < 4; ++c)
            dst[32 * c] = src[32 * c];
    }
}

// Phase A over one chunk: warp=(d-group g of 256 dims, row-quarter h)
// lane owns f-rows j1=lane, j2=32+(lane&15); 4 q-rows broadcast.
template<bool ACCUM>
__device__ __forceinline__ void phaseA(const ulonglong2* __restrict__ tileU,
                                       float* __restrict__ red, int tid)
{
    const int w    = tid >> 5;
    const int lane = tid & 31;
    const int g    = w & 1;
    const int h    = w >> 1;          // 0..3 -> q rows 4h..4h+3
    const int base = g * 64;

    const int fs1 = lane * PITCH4;
    const int fs2 = (32 + (lane & 15)) * PITCH4;
    int qs[4];
    #pragma unroll
    for (int i = 0; i < 4; ++i) qs[i] = (4 * h + i) * PITCH4;

    u64 acc1[4], acc2[4];
    #pragma unroll
    for (int i = 0; i < 4; ++i) { acc1[i] = 0ull; acc2[i] = 0ull; }

    #pragma unroll 8
    for (int step = 0; step < 64; ++step) {
        const int col = base + step;
        const ulonglong2 f1 = tileU[fs1 + col];      // strided, conflict-free
        const ulonglong2 f2 = tileU[fs2 + col];      // half-dup rows, conflict-free
        #pragma unroll
        for (int i = 0; i < 4; ++i) {
            const ulonglong2 q = tileU[qs[i] + col]; // broadcast: 1 wavefront
            fma2(acc1[i], q.x, f1.x);
            fma2(acc1[i], q.y, f1.y);
            fma2(acc2[i], q.x, f2.x);
            fma2(acc2[i], q.y, f2.y);
        }
    }

    float* myred = red + g * (S_TILE * COLS) + 4 * h * COLS;
    #pragma unroll
    for (int i = 0; i < 4; ++i) {
        if (ACCUM) myred[i * COLS + lane] += sum2(acc1[i]);
        else       myred[i * COLS + lane]  = sum2(acc1[i]);
    }
    if (lane < 16) {
        #pragma unroll
        for (int i = 0; i < 4; ++i) {
            if (ACCUM) myred[i * COLS + 32 + lane] += sum2(acc2[i]);
            else       myred[i * COLS + 32 + lane]  = sum2(acc2[i]);
        }
    }
}

// Phase B over one chunk: 16 rows x 128 f4 cols; weights broadcast LDS.128
__device__ __forceinline__ void phaseB(const ulonglong2* __restrict__ tileU,
                                       const u64* __restrict__ Wd,
                                       float4* __restrict__ out4,
                                       int s0, int cOff, int tid, int S)
{
    const int a = tid >> 7;     // rows a*8 .. a*8+7
    const int b = tid & 127;    // f4 col within chunk

    u64 acc[8][2];
    #pragma unroll
    for (int ii = 0; ii < 8; ++ii) { acc[ii][0] = 0ull; acc[ii][1] = 0ull; }

    #pragma unroll 4
    for (int jp = 0; jp < 24; ++jp) {
        const int jl = jp * 2;
        const ulonglong2 f1 = tileU[jl * PITCH4 + b];
        const ulonglong2 f2 = tileU[(jl + 1) * PITCH4 + b];
        #pragma unroll
        for (int ii = 0; ii < 8; ++ii) {
            const ulonglong2 wp =
                *reinterpret_cast<const ulonglong2*>(&Wd[(a * 8 + ii) * COLS + jl]);
            fma2(acc[ii][0], wp.x, f1.x);
            fma2(acc[ii][1], wp.x, f1.y);
            fma2(acc[ii][0], wp.y, f2.x);
            fma2(acc[ii][1], wp.y, f2.y);
        }
    }

    #pragma unroll
    for (int ii = 0; ii < 8; ++ii) {
        const int s = s0 + a * 8 + ii;
        if (s < S) {
            const float2 lo = *reinterpret_cast<float2*>(&acc[ii][0]);
            const float2 hi = *reinterpret_cast<float2*>(&acc[ii][1]);
            out4[(size_t)s * D4 + cOff + b] = make_float4(lo.x, lo.y, hi.x, hi.y);
        }
    }
}

__global__ __launch_bounds__(256, 2)
void future_encoder_kernel(const float* __restrict__ in,
                           float* __restrict__ out,
                           int S)
{
    extern __shared__ float smem[];
    float4*     tile4 = reinterpret_cast<float4*>(smem);
    ulonglong2* tileU = reinterpret_cast<ulonglong2*>(smem);
    float*      red   = smem + RED_OFF;
    u64*        Wd    = reinterpret_cast<u64*>(smem + W_OFF);
    float2*     Wd2   = reinterpret_cast<float2*>(smem + W_OFF);

    const int tid = threadIdx.x;
    const int s0  = blockIdx.x * S_TILE;
    const int bb  = blockIdx.y;

    const float4* in4  = reinterpret_cast<const float4*>(in)  + (size_t)bb * S * D4;
    float4*       out4 = reinterpret_cast<float4*>(out)       + (size_t)bb * S * D4;

    // ---- scores: chunk 0 then chunk 1 accumulate ----
    load_chunk(tile4, in4, s0, 0, tid, S);
    __syncthreads();
    phaseA<false>(tileU, red, tid);
    __syncthreads();                 // tile reads done before overwrite
    load_chunk(tile4, in4, s0, C4, tid, S);
    __syncthreads();
    phaseA<true>(tileU, red, tid);
    __syncthreads();                 // red complete

    // ---- mask + softmax (8 warps x 2 rows), write duplicated weights ----
    {
        const int w    = tid >> 5;
        const int lane = tid & 31;
        #pragma unroll
        for (int rr = 0; rr < 2; ++rr) {
            const int row = w * 2 + rr;
            float s1 = red[row * COLS + lane]
                     + red[S_TILE * COLS + row * COLS + lane];
            float s2 = 0.0f;
            if (lane < 16)
                s2 = red[row * COLS + 32 + lane]
                   + red[S_TILE * COLS + row * COLS + 32 + lane];

            const int j1 = lane;
            const int k1 = j1 - row - 1;
            const bool val1 = (k1 >= 0) && (k1 < KF) && (s0 + j1 < S);
            const float v1 = val1 ? s1 : NEG_BIG;

            const int j2 = 32 + lane;
            const int k2 = j2 - row - 1;
            const bool val2 = (lane < 16) && (k2 >= 0) && (k2 < KF) && (s0 + j2 < S);
            const float v2 = val2 ? s2 : NEG_BIG;

            float m = fmaxf(v1, v2);
            #pragma unroll
            for (int o = 16; o > 0; o >>= 1)
                m = fmaxf(m, __shfl_xor_sync(0xFFFFFFFFu, m, o));

            const float e1 = __expf(v1 - m);
            const float e2 = (lane < 16) ? __expf(v2 - m) : 0.0f;
            float sum = e1 + e2;
            #pragma unroll
            for (int o = 16; o > 0; o >>= 1)
                sum += __shfl_xor_sync(0xFFFFFFFFu, sum, o);
            const float inv = 1.0f / sum;

            const float w1 = val1 ? e1 * inv : 0.0f;
            Wd2[row * COLS + j1] = make_float2(w1, w1);
            if (lane < 16) {
                const float w2 = val2 ? e2 * inv : 0.0f;
                Wd2[row * COLS + j2] = make_float2(w2, w2);
            }
        }
    }
    __syncthreads();                 // weights ready

    // ---- output: chunk 1 (resident), then reload chunk 0 ----
    phaseB(tileU, Wd, out4, s0, C4, tid, S);
    __syncthreads();                 // tile reads done
    load_chunk(tile4, in4, s0, 0, tid, S);
    __syncthreads();
    phaseB(tileU, Wd, out4, s0, 0, tid, S);
}

extern "C" void kernel_launch(void* const* d_in, const int* in_sizes, int n_in,
                              void* d_out, int out_size)
{
    (void)n_in; (void)out_size;
    const float* in = (const float*)d_in[0];
    float* out = (float*)d_out;

    const int S = 2048;
    const int B = in_sizes[0] / (S * DCONST);

    cudaFuncSetAttribute(future_encoder_kernel,
                         cudaFuncAttributeMaxDynamicSharedMemorySize,
                         SMEM_BYTES);

    dim3 grid(S / S_TILE, B);   // 128 x B small CTAs, 2 per SM
    future_encoder_kernel<<<grid, 256, SMEM_BYTES>>>(in, out, S);
}